// round 2
// baseline (speedup 1.0000x reference)
#include <cuda_runtime.h>

#define LOG2E 1.4426950408889634f

__device__ __forceinline__ float fast_ex2(float t) {
    float r;
    asm("ex2.approx.ftz.f32 %0, %1;" : "=f"(r) : "f"(t));
    return r;
}
__device__ __forceinline__ float fast_rcp(float t) {
    float r;
    asm("rcp.approx.ftz.f32 %0, %1;" : "=f"(r) : "f"(t));
    return r;
}

struct Params {
    float w1a[8], w1b[8], b1[8], m1[8];   // layer 1: h = x0*w1a + x1*w1b + b1 ; sig arg = m1*h
    float w2[8][4], b2[4], m2[4];         // layer 2 (a1 folded into w2)
    float w3[4], b3;                      // layer 3 (a2 folded into w3)
};

__device__ __forceinline__ float row_eval(float x0, float x1, const Params& P) {
    float g[8];
#pragma unroll
    for (int j = 0; j < 8; j++) {
        float h = fmaf(x0, P.w1a[j], fmaf(x1, P.w1b[j], P.b1[j]));
        float s = fast_rcp(1.0f + fast_ex2(P.m1[j] * h));
        g[j] = h * s;               // a1 folded into W2
    }
    float o = P.b3;
#pragma unroll
    for (int j = 0; j < 4; j++) {
        float z = P.b2[j];
#pragma unroll
        for (int i = 0; i < 8; i++)
            z = fmaf(g[i], P.w2[i][j], z);
        float s = fast_rcp(1.0f + fast_ex2(P.m2[j] * z));
        o = fmaf(z * s, P.w3[j], o); // a2 folded into W3
    }
    return o;
}

__global__ __launch_bounds__(256)
void moth_mlp_kernel(const float4* __restrict__ x4,
                     const float* __restrict__ W1, const float* __restrict__ b1,
                     const float* __restrict__ a1, const float* __restrict__ c1,
                     const float* __restrict__ W2, const float* __restrict__ b2,
                     const float* __restrict__ a2, const float* __restrict__ c2,
                     const float* __restrict__ W3, const float* __restrict__ b3,
                     float2* __restrict__ out2,
                     int npairs, int nrows)
{
    Params P;
#pragma unroll
    for (int j = 0; j < 8; j++) {
        P.w1a[j] = W1[j];
        P.w1b[j] = W1[8 + j];
        P.b1[j]  = b1[j];
        P.m1[j]  = -c1[j] * LOG2E;
    }
#pragma unroll
    for (int i = 0; i < 8; i++) {
        float a = a1[i];
#pragma unroll
        for (int j = 0; j < 4; j++)
            P.w2[i][j] = a * W2[i * 4 + j];
    }
#pragma unroll
    for (int j = 0; j < 4; j++) {
        P.b2[j] = b2[j];
        P.m2[j] = -c2[j] * LOG2E;
        P.w3[j] = a2[j] * W3[j];
    }
    P.b3 = b3[0];

    const int stride = gridDim.x * blockDim.x;
    int tid = blockIdx.x * blockDim.x + threadIdx.x;

    for (int p = tid; p < npairs; p += stride) {
        float4 xx = x4[p];                 // two rows: (x,y) and (z,w)
        float oa = row_eval(xx.x, xx.y, P);
        float ob = row_eval(xx.z, xx.w, P);
        out2[p] = make_float2(oa, ob);
    }

    // odd-row tail (not hit for B = 8388608, kept for safety)
    if ((nrows & 1) && tid == 0) {
        const float2* x2 = reinterpret_cast<const float2*>(x4);
        float2 xr = x2[nrows - 1];
        reinterpret_cast<float*>(out2)[nrows - 1] = row_eval(xr.x, xr.y, P);
    }
}

extern "C" void kernel_launch(void* const* d_in, const int* in_sizes, int n_in,
                              void* d_out, int out_size)
{
    const float4* x4 = (const float4*)d_in[0];
    const float* W1 = (const float*)d_in[1];
    const float* b1 = (const float*)d_in[2];
    const float* a1 = (const float*)d_in[3];
    const float* c1 = (const float*)d_in[4];
    const float* W2 = (const float*)d_in[5];
    const float* b2 = (const float*)d_in[6];
    const float* a2 = (const float*)d_in[7];
    const float* c2 = (const float*)d_in[8];
    const float* W3 = (const float*)d_in[9];
    const float* b3 = (const float*)d_in[10];

    int nrows = in_sizes[0] / 2;   // x is [B, 2]
    int npairs = nrows / 2;

    const int threads = 256;
    const int blocks = 1184;       // 148 SMs * 8; grid-stride

    moth_mlp_kernel<<<blocks, threads>>>(x4, W1, b1, a1, c1, W2, b2, a2, c2, W3, b3,
                                         (float2*)d_out, npairs, nrows);
}